// round 1
// baseline (speedup 1.0000x reference)
#include <cuda_runtime.h>
#include <math.h>

namespace {

constexpr int DKP = 28;              // padded factor dim (25 -> 28, 16B aligned)
constexpr int NDIM = 2 * DKP;        // 56 floats = 224B per node
constexpr int TOTAL_NODES = 180000;  // 60000 + 30000 + 6*15000
constexpr int TOTAL_ROWS  = 270000;  // 60000 + 7*30000
constexpr int TOTAL_COLS  = 180000;  // 30000 + 60000 + 6*15000
constexpr int TOTAL_EDGES = 3800000; // 2*1e6 + 6*3e5
constexpr int OUT_ROWS = 90000;
constexpr int SCAN_NBLK = (TOTAL_ROWS + 1023) / 1024; // 264

__constant__ int c_EOFF[9] = {0,1000000,2000000,2300000,2600000,2900000,3200000,3500000,3800000};
__constant__ int c_ROFF[9] = {0,60000,90000,120000,150000,180000,210000,240000,270000};
__constant__ int c_COFF[9] = {0,30000,90000,105000,120000,135000,150000,165000,180000};
__constant__ int c_TOFF[9] = {0,60000,90000,105000,120000,135000,150000,165000,180000};
__constant__ int c_SRC[8]  = {0,1,1,1,1,1,1,1};
__constant__ int c_DST[8]  = {1,0,2,3,4,5,6,7};

__device__ float g_emb[(size_t)TOTAL_NODES * NDIM + 16]; // projected embeddings, pads zero
__device__ float g_z  [(size_t)TOTAL_ROWS  * NDIM];      // per-relation messages
__device__ float g_p  [TOTAL_ROWS * 2];
__device__ float g_q  [TOTAL_COLS * 2];
__device__ float g_r  [TOTAL_ROWS * 2];
__device__ int   g_rowcnt[TOTAL_ROWS];
__device__ int   g_rowptr[TOTAL_ROWS + 1];
__device__ int   g_blocksum[SCAN_NBLK];
__device__ int   g_fill[TOTAL_ROWS];
__device__ int   g_colidx[TOTAL_EDGES];

struct Ptrs {
    const int*   edge[8];
    const float* embin[8];
    const float* Wtk;
    const float* at;
    const float* W;
    const float* q_rela;
};

__device__ __forceinline__ int find_seg8(const int* off, int x) {
    int e = 0;
    #pragma unroll
    for (int i = 1; i < 8; i++) e += (x >= off[i]);
    return e;
}

// ---------------- initial projection: embs[t] = l2n(lrelu(emb_in[t] @ Wtk[t])) ----
__global__ void __launch_bounds__(128) k_init(Ptrs P) {
    __shared__ float Wsh[2][2][50 * 25];   // [which-type][k][d*25+f]
    int base_slot = blockIdx.x * 128;
    int node0 = base_slot >> 1;
    int nlast = (base_slot + 127) >> 1;
    if (nlast > TOTAL_NODES - 1) nlast = TOTAL_NODES - 1;
    int t0 = find_seg8(c_TOFF, node0);
    int t1 = find_seg8(c_TOFF, nlast);
    for (int i = threadIdx.x; i < 2 * 50 * 25; i += 128) {
        Wsh[0][0][i] = P.Wtk[(size_t)t0 * 2 * 50 * 25 + i];
        Wsh[1][0][i] = P.Wtk[(size_t)t1 * 2 * 50 * 25 + i];
    }
    __syncthreads();
    int slot = base_slot + threadIdx.x;
    if (slot >= TOTAL_NODES * 2) return;
    int node = slot >> 1, k = slot & 1;
    int t = find_seg8(c_TOFF, node);
    int sel = (t == t0) ? 0 : 1;
    const float* x = P.embin[t] + (size_t)(node - c_TOFF[t]) * 50;
    const float* w = &Wsh[sel][k][0];
    float out[25];
    #pragma unroll
    for (int f = 0; f < 25; f++) out[f] = 0.f;
    for (int d = 0; d < 50; d++) {
        float xd = __ldg(&x[d]);
        #pragma unroll
        for (int f = 0; f < 25; f++) out[f] += xd * w[d * 25 + f];
    }
    float nrm = 0.f;
    #pragma unroll
    for (int f = 0; f < 25; f++) {
        float s = out[f];
        s = (s >= 0.f) ? s : 0.2f * s;
        out[f] = s;
        nrm += s * s;
    }
    float inv = 1.f / fmaxf(sqrtf(nrm), 1e-12f);
    float* dst = g_emb + (size_t)node * NDIM + k * DKP;
    #pragma unroll
    for (int f = 0; f < 25; f++) dst[f] = out[f] * inv;
    dst[25] = 0.f; dst[26] = 0.f; dst[27] = 0.f;
}

// ---------------- CSR build (edges constant across iterations) --------------------
__global__ void k_hist(Ptrs P) {
    int j = blockIdx.x * blockDim.x + threadIdx.x;
    if (j >= TOTAL_EDGES) return;
    int e = find_seg8(c_EOFF, j);
    int le = j - c_EOFF[e];
    int u = P.edge[e][le];
    atomicAdd(&g_rowcnt[c_ROFF[e] + u], 1);
}

__global__ void k_scan1() {
    __shared__ int sh[1024];
    int i = blockIdx.x * 1024 + threadIdx.x;
    int v = (i < TOTAL_ROWS) ? g_rowcnt[i] : 0;
    sh[threadIdx.x] = v;
    __syncthreads();
    for (int off = 1; off < 1024; off <<= 1) {
        int t = (threadIdx.x >= off) ? sh[threadIdx.x - off] : 0;
        __syncthreads();
        sh[threadIdx.x] += t;
        __syncthreads();
    }
    if (i < TOTAL_ROWS) g_rowptr[i] = sh[threadIdx.x] - v;
    if (threadIdx.x == 1023) g_blocksum[blockIdx.x] = sh[1023];
}

__global__ void k_scan2() {
    __shared__ int sh[512];
    int tid = threadIdx.x;
    int v = (tid < SCAN_NBLK) ? g_blocksum[tid] : 0;
    sh[tid] = v;
    __syncthreads();
    for (int off = 1; off < 512; off <<= 1) {
        int t = (tid >= off) ? sh[tid - off] : 0;
        __syncthreads();
        sh[tid] += t;
        __syncthreads();
    }
    if (tid < SCAN_NBLK) g_blocksum[tid] = sh[tid] - v;  // exclusive
}

__global__ void k_scan3() {
    int i = blockIdx.x * blockDim.x + threadIdx.x;
    if (i < TOTAL_ROWS) g_rowptr[i] += g_blocksum[i >> 10];
    if (i == 0) g_rowptr[TOTAL_ROWS] = TOTAL_EDGES;
}

__global__ void k_fill(Ptrs P) {
    int j = blockIdx.x * blockDim.x + threadIdx.x;
    if (j >= TOTAL_EDGES) return;
    int e = find_seg8(c_EOFF, j);
    int le = j - c_EOFF[e];
    int E = c_EOFF[e + 1] - c_EOFF[e];
    const int* ed = P.edge[e];
    int u = ed[le], c = ed[E + le];
    int row = c_ROFF[e] + u;
    int pos = g_rowptr[row] + atomicAdd(&g_fill[row], 1);
    g_colidx[pos] = c;
}

// ---------------- per-node attention projections p,q ------------------------------
__global__ void __launch_bounds__(256) k_pq(Ptrs P) {
    int slot = blockIdx.x * 256 + threadIdx.x;
    if (slot >= TOTAL_ROWS + TOTAL_COLS) return;
    if (slot < TOTAL_ROWS) {
        int e = find_seg8(c_ROFF, slot);
        int n = slot - c_ROFF[e];
        const float* er = g_emb + (size_t)(c_TOFF[c_SRC[e]] + n) * NDIM;
        #pragma unroll
        for (int k = 0; k < 2; k++) {
            const float* a = P.at + (e * 2 + k) * 50;
            float sm = 0.f;
            #pragma unroll
            for (int d = 0; d < 25; d++) sm += er[k * DKP + d] * __ldg(&a[d]);
            g_p[slot * 2 + k] = sm;
        }
    } else {
        int col = slot - TOTAL_ROWS;
        int e = find_seg8(c_COFF, col);
        int n = col - c_COFF[e];
        const float* er = g_emb + (size_t)(c_TOFF[c_DST[e]] + n) * NDIM;
        #pragma unroll
        for (int k = 0; k < 2; k++) {
            const float* a = P.at + (e * 2 + k) * 50 + 25;
            float sm = 0.f;
            #pragma unroll
            for (int d = 0; d < 25; d++) sm += er[k * DKP + d] * __ldg(&a[d]);
            g_q[col * 2 + k] = sm;
        }
    }
}

// ---------------- fused score + row-softmax + aggregate (warp per row) ------------
__global__ void __launch_bounds__(256) k_row(Ptrs /*unused*/) {
    int row  = (blockIdx.x * 256 + threadIdx.x) >> 5;
    int lane = threadIdx.x & 31;
    if (row >= TOTAL_ROWS) return;
    int e = find_seg8(c_ROFF, row);
    int base = g_rowptr[row];
    int deg  = g_rowptr[row + 1] - base;
    float* zr = g_z + (size_t)row * NDIM;
    if (deg == 0) {
        zr[lane] = 0.f;
        if (lane < 24) zr[32 + lane] = 0.f;
        return;
    }
    int coff  = c_COFF[e];
    int nbase = c_TOFF[c_DST[e]];
    float2 pv = ((const float2*)g_p)[row];

    // online softmax over the row's edges: val = 0.5*(relu(p0+q0)+relu(p1+q1))
    float m = -1e30f, s = 0.f;
    for (int i = lane; i < deg; i += 32) {
        int c = g_colidx[base + i];
        float2 qv = ((const float2*)g_q)[coff + c];
        float v = 0.5f * (fmaxf(pv.x + qv.x, 0.f) + fmaxf(pv.y + qv.y, 0.f));
        float mN = fmaxf(m, v);
        s = s * expf(m - mN) + expf(v - mN);
        m = mN;
    }
    #pragma unroll
    for (int off = 16; off; off >>= 1) {
        float mo = __shfl_xor_sync(0xffffffffu, m, off);
        float so = __shfl_xor_sync(0xffffffffu, s, off);
        float mN = fmaxf(m, mo);
        s = s * expf(m - mN) + so * expf(mo - mN);
        m = mN;
    }
    float invS = 1.f / s;

    // aggregate attn-weighted neighbor features; lanes own output dims
    float acc0 = 0.f, acc1 = 0.f;
    for (int i0 = 0; i0 < deg; i0 += 32) {
        int i = i0 + lane;
        int c = 0; float a = 0.f;
        if (i < deg) {
            c = g_colidx[base + i];
            float2 qv = ((const float2*)g_q)[coff + c];
            float v = 0.5f * (fmaxf(pv.x + qv.x, 0.f) + fmaxf(pv.y + qv.y, 0.f));
            a = expf(v - m) * invS;
        }
        int nn = deg - i0; if (nn > 32) nn = 32;
        for (int jj = 0; jj < nn; jj++) {
            float aj = __shfl_sync(0xffffffffu, a, jj);
            int   cj = __shfl_sync(0xffffffffu, c, jj);
            const float* er = g_emb + (size_t)(nbase + cj) * NDIM;
            acc0 += aj * er[lane];
            if (lane < 24) acc1 += aj * er[32 + lane];
        }
    }
    zr[lane] = acc0;
    if (lane < 24) zr[32 + lane] = acc1;
}

// ---------------- z' = lrelu(z) @ W ; r = softmax_k( tanh(z') . q_rela ) ----------
__global__ void __launch_bounds__(128) k_transform(Ptrs P) {
    __shared__ float Ws[625];
    for (int i = threadIdx.x; i < 625; i += 128) Ws[i] = P.W[i];
    __syncthreads();
    int row = blockIdx.x * 128 + threadIdx.x;
    if (row >= TOTAL_ROWS) return;
    int e = find_seg8(c_ROFF, row);
    const float* qr = P.q_rela + e * 25;
    float* zr = g_z + (size_t)row * NDIM;
    float s01[2];
    #pragma unroll
    for (int k = 0; k < 2; k++) {
        float lr[25];
        #pragma unroll
        for (int d = 0; d < 25; d++) {
            float v = zr[k * DKP + d];
            lr[d] = (v >= 0.f) ? v : 0.2f * v;
        }
        float sk = 0.f;
        for (int f = 0; f < 25; f++) {
            float sm = 0.f;
            #pragma unroll
            for (int d = 0; d < 25; d++) sm += lr[d] * Ws[d * 25 + f];
            zr[k * DKP + f] = sm;
            sk += tanhf(sm) * __ldg(&qr[f]);
        }
        s01[k] = sk;
    }
    float mm = fmaxf(s01[0], s01[1]);
    float e0 = expf(s01[0] - mm), e1 = expf(s01[1] - mm);
    float inv = 1.f / (e0 + e1);
    g_r[row * 2 + 0] = e0 * inv;
    g_r[row * 2 + 1] = e1 * inv;
}

// ---------------- ego aggregation + l2 normalize (types 0 and 1 only) -------------
__global__ void __launch_bounds__(256) k_agg() {
    int slot = blockIdx.x * 256 + threadIdx.x;
    if (slot >= OUT_ROWS * 2) return;
    int node = slot >> 1, k = slot & 1;
    float acc[25];
    float* er = g_emb + (size_t)node * NDIM + k * DKP;
    #pragma unroll
    for (int d = 0; d < 25; d++) acc[d] = er[d];
    if (node < 60000) {                 // type 0: relation 0 only
        float r = g_r[node * 2 + k];
        const float* zz = g_z + (size_t)node * NDIM + k * DKP;
        #pragma unroll
        for (int d = 0; d < 25; d++) acc[d] += r * zz[d];
    } else {                            // type 1: relations 1..7
        int n = node - 60000;
        #pragma unroll
        for (int e = 1; e < 8; e++) {
            int row = c_ROFF[e] + n;
            float r = g_r[row * 2 + k];
            const float* zz = g_z + (size_t)row * NDIM + k * DKP;
            #pragma unroll
            for (int d = 0; d < 25; d++) acc[d] += r * zz[d];
        }
    }
    float nrm = 0.f;
    #pragma unroll
    for (int d = 0; d < 25; d++) nrm += acc[d] * acc[d];
    float inv = 1.f / fmaxf(sqrtf(nrm), 1e-12f);
    #pragma unroll
    for (int d = 0; d < 25; d++) er[d] = acc[d] * inv;
}

// ---------------- output: [n, k*25+d] for user then item --------------------------
__global__ void k_out(float* __restrict__ out) {
    int idx = blockIdx.x * blockDim.x + threadIdx.x;
    if (idx >= OUT_ROWS * 50) return;
    int r = idx / 50, c = idx - r * 50;
    int k = c / 25, d = c - k * 25;
    out[idx] = g_emb[(size_t)r * NDIM + k * DKP + d];
}

} // anonymous namespace

extern "C" void kernel_launch(void* const* d_in, const int* in_sizes, int n_in,
                              void* d_out, int out_size) {
    Ptrs P;
    for (int i = 0; i < 8; i++) P.edge[i]  = (const int*)d_in[i];
    for (int i = 0; i < 8; i++) P.embin[i] = (const float*)d_in[8 + i];
    P.Wtk    = (const float*)d_in[16];
    P.at     = (const float*)d_in[17];
    P.W      = (const float*)d_in[18];
    P.q_rela = (const float*)d_in[19];

    void* p_rowcnt = nullptr; void* p_fill = nullptr;
    cudaGetSymbolAddress(&p_rowcnt, g_rowcnt);
    cudaGetSymbolAddress(&p_fill, g_fill);

    k_init<<<(TOTAL_NODES * 2 + 127) / 128, 128>>>(P);

    cudaMemsetAsync(p_rowcnt, 0, sizeof(int) * TOTAL_ROWS, 0);
    cudaMemsetAsync(p_fill,   0, sizeof(int) * TOTAL_ROWS, 0);
    k_hist<<<(TOTAL_EDGES + 255) / 256, 256>>>(P);
    k_scan1<<<SCAN_NBLK, 1024>>>();
    k_scan2<<<1, 512>>>();
    k_scan3<<<(TOTAL_ROWS + 255) / 256, 256>>>();
    k_fill<<<(TOTAL_EDGES + 255) / 256, 256>>>(P);

    for (int it = 0; it < 4; it++) {
        k_pq<<<(TOTAL_ROWS + TOTAL_COLS + 255) / 256, 256>>>(P);
        k_row<<<(TOTAL_ROWS * 32 + 255) / 256, 256>>>(P);
        k_transform<<<(TOTAL_ROWS + 127) / 128, 128>>>(P);
        k_agg<<<(OUT_ROWS * 2 + 255) / 256, 256>>>();
    }
    k_out<<<(OUT_ROWS * 50 + 255) / 256, 256>>>((float*)d_out);
}

// round 2
// speedup vs baseline: 1.0414x; 1.0414x over previous
#include <cuda_runtime.h>
#include <math.h>

namespace {

constexpr int DKP = 28;              // padded factor dim (25 -> 28, 16B aligned)
constexpr int NDIM = 2 * DKP;        // 56 floats = 224B per node
constexpr int TOTAL_NODES = 180000;  // 60000 + 30000 + 6*15000
constexpr int TOTAL_ROWS  = 270000;  // 60000 + 7*30000
constexpr int TOTAL_COLS  = 180000;  // 30000 + 60000 + 6*15000
constexpr int TOTAL_EDGES = 3800000; // 2*1e6 + 6*3e5
constexpr int OUT_ROWS = 90000;
constexpr int SCAN_NBLK = (TOTAL_ROWS + 1023) / 1024; // 264

__constant__ int c_EOFF[9] = {0,1000000,2000000,2300000,2600000,2900000,3200000,3500000,3800000};
__constant__ int c_ROFF[9] = {0,60000,90000,120000,150000,180000,210000,240000,270000};
__constant__ int c_COFF[9] = {0,30000,90000,105000,120000,135000,150000,165000,180000};
__constant__ int c_TOFF[9] = {0,60000,90000,105000,120000,135000,150000,165000,180000};
__constant__ int c_SRC[8]  = {0,1,1,1,1,1,1,1};
__constant__ int c_DST[8]  = {1,0,2,3,4,5,6,7};

__device__ float g_emb[(size_t)TOTAL_NODES * NDIM + 16]; // projected embeddings, pads zero
__device__ float g_z  [(size_t)TOTAL_ROWS  * NDIM];      // per-relation messages
__device__ float g_p  [TOTAL_ROWS * 2];
__device__ float g_q  [TOTAL_COLS * 2];
__device__ float g_r  [TOTAL_ROWS * 2];
__device__ int   g_rowcnt[TOTAL_ROWS];
__device__ int   g_rowptr[TOTAL_ROWS + 1];
__device__ int   g_blocksum[SCAN_NBLK];
__device__ int   g_fill[TOTAL_ROWS];
__device__ int   g_colidx[TOTAL_EDGES];

struct Ptrs {
    const int*   edge[8];
    const float* embin[8];
    const float* Wtk;
    const float* at;
    const float* W;
    const float* q_rela;
};

__device__ __forceinline__ int find_seg8(const int* off, int x) {
    int e = 0;
    #pragma unroll
    for (int i = 1; i < 8; i++) e += (x >= off[i]);
    return e;
}

__device__ __forceinline__ float fast_tanh(float x) {
    float y;
    asm("tanh.approx.f32 %0, %1;" : "=f"(y) : "f"(x));
    return y;
}

// ---------------- initial projection: embs[t] = l2n(lrelu(emb_in[t] @ Wtk[t])) ----
__global__ void __launch_bounds__(128) k_init(Ptrs P) {
    __shared__ float Wsh[2][2][50 * 25];   // [which-type][k][d*25+f]
    int base_slot = blockIdx.x * 128;
    int node0 = base_slot >> 1;
    int nlast = (base_slot + 127) >> 1;
    if (nlast > TOTAL_NODES - 1) nlast = TOTAL_NODES - 1;
    int t0 = find_seg8(c_TOFF, node0);
    int t1 = find_seg8(c_TOFF, nlast);
    for (int i = threadIdx.x; i < 2 * 50 * 25; i += 128) {
        Wsh[0][0][i] = P.Wtk[(size_t)t0 * 2 * 50 * 25 + i];
        Wsh[1][0][i] = P.Wtk[(size_t)t1 * 2 * 50 * 25 + i];
    }
    __syncthreads();
    int slot = base_slot + threadIdx.x;
    if (slot >= TOTAL_NODES * 2) return;
    int node = slot >> 1, k = slot & 1;
    int t = find_seg8(c_TOFF, node);
    int sel = (t == t0) ? 0 : 1;
    const float* x = P.embin[t] + (size_t)(node - c_TOFF[t]) * 50;
    const float* w = &Wsh[sel][k][0];
    float out[25];
    #pragma unroll
    for (int f = 0; f < 25; f++) out[f] = 0.f;
    for (int d = 0; d < 50; d++) {
        float xd = __ldg(&x[d]);
        #pragma unroll
        for (int f = 0; f < 25; f++) out[f] += xd * w[d * 25 + f];
    }
    float nrm = 0.f;
    #pragma unroll
    for (int f = 0; f < 25; f++) {
        float s = out[f];
        s = (s >= 0.f) ? s : 0.2f * s;
        out[f] = s;
        nrm += s * s;
    }
    float inv = 1.f / fmaxf(sqrtf(nrm), 1e-12f);
    float* dst = g_emb + (size_t)node * NDIM + k * DKP;
    #pragma unroll
    for (int f = 0; f < 25; f++) dst[f] = out[f] * inv;
    dst[25] = 0.f; dst[26] = 0.f; dst[27] = 0.f;
}

// ---------------- CSR build (edges constant across iterations) --------------------
__global__ void k_hist(Ptrs P) {
    int j = blockIdx.x * blockDim.x + threadIdx.x;
    if (j >= TOTAL_EDGES) return;
    int e = find_seg8(c_EOFF, j);
    int le = j - c_EOFF[e];
    int u = P.edge[e][le];
    atomicAdd(&g_rowcnt[c_ROFF[e] + u], 1);
}

__global__ void k_scan1() {
    __shared__ int sh[1024];
    int i = blockIdx.x * 1024 + threadIdx.x;
    int v = (i < TOTAL_ROWS) ? g_rowcnt[i] : 0;
    sh[threadIdx.x] = v;
    __syncthreads();
    for (int off = 1; off < 1024; off <<= 1) {
        int t = (threadIdx.x >= off) ? sh[threadIdx.x - off] : 0;
        __syncthreads();
        sh[threadIdx.x] += t;
        __syncthreads();
    }
    if (i < TOTAL_ROWS) g_rowptr[i] = sh[threadIdx.x] - v;
    if (threadIdx.x == 1023) g_blocksum[blockIdx.x] = sh[1023];
}

__global__ void k_scan2() {
    __shared__ int sh[512];
    int tid = threadIdx.x;
    int v = (tid < SCAN_NBLK) ? g_blocksum[tid] : 0;
    sh[tid] = v;
    __syncthreads();
    for (int off = 1; off < 512; off <<= 1) {
        int t = (tid >= off) ? sh[tid - off] : 0;
        __syncthreads();
        sh[tid] += t;
        __syncthreads();
    }
    if (tid < SCAN_NBLK) g_blocksum[tid] = sh[tid] - v;  // exclusive
}

__global__ void k_scan3() {
    int i = blockIdx.x * blockDim.x + threadIdx.x;
    if (i < TOTAL_ROWS) g_rowptr[i] += g_blocksum[i >> 10];
    if (i == 0) g_rowptr[TOTAL_ROWS] = TOTAL_EDGES;
}

__global__ void k_fill(Ptrs P) {
    int j = blockIdx.x * blockDim.x + threadIdx.x;
    if (j >= TOTAL_EDGES) return;
    int e = find_seg8(c_EOFF, j);
    int le = j - c_EOFF[e];
    int E = c_EOFF[e + 1] - c_EOFF[e];
    const int* ed = P.edge[e];
    int u = ed[le], c = ed[E + le];
    int row = c_ROFF[e] + u;
    int pos = g_rowptr[row] + atomicAdd(&g_fill[row], 1);
    g_colidx[pos] = c;
}

// ---------------- per-node attention projections p,q ------------------------------
__global__ void __launch_bounds__(256) k_pq(Ptrs P) {
    int slot = blockIdx.x * 256 + threadIdx.x;
    if (slot >= TOTAL_ROWS + TOTAL_COLS) return;
    if (slot < TOTAL_ROWS) {
        int e = find_seg8(c_ROFF, slot);
        int n = slot - c_ROFF[e];
        const float* er = g_emb + (size_t)(c_TOFF[c_SRC[e]] + n) * NDIM;
        #pragma unroll
        for (int k = 0; k < 2; k++) {
            const float* a = P.at + (e * 2 + k) * 50;
            float sm = 0.f;
            #pragma unroll
            for (int d = 0; d < 25; d++) sm += er[k * DKP + d] * __ldg(&a[d]);
            g_p[slot * 2 + k] = sm;
        }
    } else {
        int col = slot - TOTAL_ROWS;
        int e = find_seg8(c_COFF, col);
        int n = col - c_COFF[e];
        const float* er = g_emb + (size_t)(c_TOFF[c_DST[e]] + n) * NDIM;
        #pragma unroll
        for (int k = 0; k < 2; k++) {
            const float* a = P.at + (e * 2 + k) * 50 + 25;
            float sm = 0.f;
            #pragma unroll
            for (int d = 0; d < 25; d++) sm += er[k * DKP + d] * __ldg(&a[d]);
            g_q[col * 2 + k] = sm;
        }
    }
}

// ---------------- fused score + softmax + aggregate, single pass (warp/row) -------
// Flash-style online softmax: per 32-edge chunk, lanes score edges in parallel,
// warp-reduce max/sum, rescale acc once, then broadcast-accumulate with float2
// lanes (lane<28 owns dims [2l,2l+1]) and 4x-unrolled loads for MLP.
__global__ void __launch_bounds__(256) k_row() {
    int row  = (blockIdx.x * 256 + threadIdx.x) >> 5;
    int lane = threadIdx.x & 31;
    if (row >= TOTAL_ROWS) return;
    int e = find_seg8(c_ROFF, row);
    int base = g_rowptr[row];
    int deg  = g_rowptr[row + 1] - base;
    float* zr = g_z + (size_t)row * NDIM;
    if (deg == 0) {
        zr[lane] = 0.f;
        if (lane < 24) zr[32 + lane] = 0.f;
        return;
    }
    int coff  = c_COFF[e];
    int nbase = c_TOFF[c_DST[e]];
    float2 pv = ((const float2*)g_p)[row];
    int dlane = (lane < 28) ? lane : 27;   // clamp: lanes 28-31 do redundant loads

    float m = -1e30f, s = 0.f;
    float2 acc = make_float2(0.f, 0.f);

    for (int i0 = 0; i0 < deg; i0 += 32) {
        int i = i0 + lane;
        int c = 0; float v = -1e30f;
        if (i < deg) {
            c = __ldg(&g_colidx[base + i]);
            float2 qv = __ldg(&((const float2*)g_q)[coff + c]);
            v = 0.5f * (fmaxf(pv.x + qv.x, 0.f) + fmaxf(pv.y + qv.y, 0.f));
        }
        // chunk max
        float cm = v;
        #pragma unroll
        for (int off = 16; off; off >>= 1)
            cm = fmaxf(cm, __shfl_xor_sync(0xffffffffu, cm, off));
        float newm = fmaxf(m, cm);
        float scale = __expf(m - newm);
        acc.x *= scale; acc.y *= scale;
        float w = __expf(v - newm);        // 0 for inactive lanes
        float cs = w;
        #pragma unroll
        for (int off = 16; off; off >>= 1)
            cs += __shfl_xor_sync(0xffffffffu, cs, off);
        s = s * scale + cs;
        m = newm;

        int nn = deg - i0; if (nn > 32) nn = 32;
        int full = nn & ~3;
        int jj = 0;
        for (; jj < full; jj += 4) {
            float a0 = __shfl_sync(0xffffffffu, w, jj + 0);
            float a1 = __shfl_sync(0xffffffffu, w, jj + 1);
            float a2 = __shfl_sync(0xffffffffu, w, jj + 2);
            float a3 = __shfl_sync(0xffffffffu, w, jj + 3);
            int   c0 = __shfl_sync(0xffffffffu, c, jj + 0);
            int   c1 = __shfl_sync(0xffffffffu, c, jj + 1);
            int   c2 = __shfl_sync(0xffffffffu, c, jj + 2);
            int   c3 = __shfl_sync(0xffffffffu, c, jj + 3);
            float2 f0 = __ldg(&((const float2*)(g_emb + (size_t)(nbase + c0) * NDIM))[dlane]);
            float2 f1 = __ldg(&((const float2*)(g_emb + (size_t)(nbase + c1) * NDIM))[dlane]);
            float2 f2 = __ldg(&((const float2*)(g_emb + (size_t)(nbase + c2) * NDIM))[dlane]);
            float2 f3 = __ldg(&((const float2*)(g_emb + (size_t)(nbase + c3) * NDIM))[dlane]);
            acc.x += a0 * f0.x; acc.y += a0 * f0.y;
            acc.x += a1 * f1.x; acc.y += a1 * f1.y;
            acc.x += a2 * f2.x; acc.y += a2 * f2.y;
            acc.x += a3 * f3.x; acc.y += a3 * f3.y;
        }
        for (; jj < nn; jj++) {
            float aj = __shfl_sync(0xffffffffu, w, jj);
            int   cj = __shfl_sync(0xffffffffu, c, jj);
            float2 fj = __ldg(&((const float2*)(g_emb + (size_t)(nbase + cj) * NDIM))[dlane]);
            acc.x += aj * fj.x; acc.y += aj * fj.y;
        }
    }
    float invS = 1.f / s;
    if (lane < 28) {
        float2 outv = make_float2(acc.x * invS, acc.y * invS);
        ((float2*)zr)[lane] = outv;
    }
}

// ---------------- z' = lrelu(z) @ W ; r = softmax_k( tanh(z') . q_rela ) ----------
__global__ void __launch_bounds__(128) k_transform(Ptrs P) {
    __shared__ float Ws[625];
    for (int i = threadIdx.x; i < 625; i += 128) Ws[i] = P.W[i];
    __syncthreads();
    int row = blockIdx.x * 128 + threadIdx.x;
    if (row >= TOTAL_ROWS) return;
    int e = find_seg8(c_ROFF, row);
    const float* qr = P.q_rela + e * 25;
    float* zr = g_z + (size_t)row * NDIM;
    float s01[2];
    #pragma unroll
    for (int k = 0; k < 2; k++) {
        float lr[25];
        #pragma unroll
        for (int d = 0; d < 25; d++) {
            float v = zr[k * DKP + d];
            lr[d] = (v >= 0.f) ? v : 0.2f * v;
        }
        float sk = 0.f;
        for (int f = 0; f < 25; f++) {
            float sm = 0.f;
            #pragma unroll
            for (int d = 0; d < 25; d++) sm += lr[d] * Ws[d * 25 + f];
            zr[k * DKP + f] = sm;
            sk += fast_tanh(sm) * __ldg(&qr[f]);
        }
        s01[k] = sk;
    }
    float mm = fmaxf(s01[0], s01[1]);
    float e0 = __expf(s01[0] - mm), e1 = __expf(s01[1] - mm);
    float inv = 1.f / (e0 + e1);
    g_r[row * 2 + 0] = e0 * inv;
    g_r[row * 2 + 1] = e1 * inv;
}

// ---------------- ego aggregation + l2 normalize (types 0 and 1 only) -------------
__global__ void __launch_bounds__(256) k_agg() {
    int slot = blockIdx.x * 256 + threadIdx.x;
    if (slot >= OUT_ROWS * 2) return;
    int node = slot >> 1, k = slot & 1;
    float acc[25];
    float* er = g_emb + (size_t)node * NDIM + k * DKP;
    #pragma unroll
    for (int d = 0; d < 25; d++) acc[d] = er[d];
    if (node < 60000) {                 // type 0: relation 0 only
        float r = g_r[node * 2 + k];
        const float* zz = g_z + (size_t)node * NDIM + k * DKP;
        #pragma unroll
        for (int d = 0; d < 25; d++) acc[d] += r * zz[d];
    } else {                            // type 1: relations 1..7
        int n = node - 60000;
        #pragma unroll
        for (int e = 1; e < 8; e++) {
            int row = c_ROFF[e] + n;
            float r = g_r[row * 2 + k];
            const float* zz = g_z + (size_t)row * NDIM + k * DKP;
            #pragma unroll
            for (int d = 0; d < 25; d++) acc[d] += r * zz[d];
        }
    }
    float nrm = 0.f;
    #pragma unroll
    for (int d = 0; d < 25; d++) nrm += acc[d] * acc[d];
    float inv = 1.f / fmaxf(sqrtf(nrm), 1e-12f);
    #pragma unroll
    for (int d = 0; d < 25; d++) er[d] = acc[d] * inv;
}

// ---------------- output: [n, k*25+d] for user then item --------------------------
__global__ void k_out(float* __restrict__ out) {
    int idx = blockIdx.x * blockDim.x + threadIdx.x;
    if (idx >= OUT_ROWS * 50) return;
    int r = idx / 50, c = idx - r * 50;
    int k = c / 25, d = c - k * 25;
    out[idx] = g_emb[(size_t)r * NDIM + k * DKP + d];
}

} // anonymous namespace

extern "C" void kernel_launch(void* const* d_in, const int* in_sizes, int n_in,
                              void* d_out, int out_size) {
    Ptrs P;
    for (int i = 0; i < 8; i++) P.edge[i]  = (const int*)d_in[i];
    for (int i = 0; i < 8; i++) P.embin[i] = (const float*)d_in[8 + i];
    P.Wtk    = (const float*)d_in[16];
    P.at     = (const float*)d_in[17];
    P.W      = (const float*)d_in[18];
    P.q_rela = (const float*)d_in[19];

    void* p_rowcnt = nullptr; void* p_fill = nullptr;
    cudaGetSymbolAddress(&p_rowcnt, g_rowcnt);
    cudaGetSymbolAddress(&p_fill, g_fill);

    k_init<<<(TOTAL_NODES * 2 + 127) / 128, 128>>>(P);

    cudaMemsetAsync(p_rowcnt, 0, sizeof(int) * TOTAL_ROWS, 0);
    cudaMemsetAsync(p_fill,   0, sizeof(int) * TOTAL_ROWS, 0);
    k_hist<<<(TOTAL_EDGES + 255) / 256, 256>>>(P);
    k_scan1<<<SCAN_NBLK, 1024>>>();
    k_scan2<<<1, 512>>>();
    k_scan3<<<(TOTAL_ROWS + 255) / 256, 256>>>();
    k_fill<<<(TOTAL_EDGES + 255) / 256, 256>>>(P);

    for (int it = 0; it < 4; it++) {
        k_pq<<<(TOTAL_ROWS + TOTAL_COLS + 255) / 256, 256>>>(P);
        k_row<<<(TOTAL_ROWS * 32 + 255) / 256, 256>>>();
        k_transform<<<(TOTAL_ROWS + 127) / 128, 128>>>(P);
        k_agg<<<(OUT_ROWS * 2 + 255) / 256, 256>>>();
    }
    k_out<<<(OUT_ROWS * 50 + 255) / 256, 256>>>((float*)d_out);
}